// round 16
// baseline (speedup 1.0000x reference)
#include <cuda_runtime.h>
#include <cuda_fp16.h>
#include <cstdint>

// DynamicPooling R16: reuse loop restructured to half-warp row pairs.
//  - one ld.global.nc.L2::evict_last.v4.b64 (32B/lane) fetches a whole row
//    pair per warp  -> LDG/row halved, y persisted in L2 vs concurrent fill
//  - width-16 dot reduction -> SHFL/row 5 -> 2, exp/row 1 -> 0.5
// Fill kernel + fork-join schedule identical to R15.
// B=64, N=4096, D=256. x f32 [B,N,D], m f32 [B,N,1]. Out: w [B,N], s [B,D].

namespace {
constexpr int Bb = 64;
constexpr int Nn = 4096;
constexpr int Dd = 256;
constexpr int NCHUNK = 32;            // N-chunks per batch
constexpr int ROWS = Nn / NCHUNK;     // 128 rows per block
constexpr int WARPS = 8;
constexpr int RPW = ROWS / WARPS;     // 16 rows per warp (8 pairs)
constexpr int PAIRS = RPW / 2;        // 8
constexpr int GRP = 16;               // batches per group
constexpr int NGRP = Bb / GRP;        // 4 groups
constexpr int PFF = 3;                // prefetch depth, fill (DRAM, f32)
constexpr int PFR = 2;                // prefetch depth, reuse (pairs)
}

__device__ __half g_y[(size_t)Bb * Nn * Dd];  // fp16 cache of m*x (128MB)
__device__ float g_part[Bb * NCHUNK * Dd];    // unnormalized sigma partials
__device__ float g_Z[Bb * NCHUNK];            // per-chunk mass
__device__ float g_b[Bb * Nn];

namespace {
struct StreamKit {
    cudaStream_t s1;
    cudaEvent_t ev_root;
    cudaEvent_t ev_fill[NGRP];
    StreamKit() {
        cudaStreamCreateWithFlags(&s1, cudaStreamNonBlocking);
        cudaEventCreateWithFlags(&ev_root, cudaEventDisableTiming);
        for (int i = 0; i < NGRP; i++)
            cudaEventCreateWithFlags(&ev_fill[i], cudaEventDisableTiming);
    }
};
StreamKit g_kit;
}

__device__ __forceinline__ unsigned int pack2h(float a, float b) {
    __half2 h = __floats2half2_rn(a, b);
    return *reinterpret_cast<unsigned int*>(&h);
}
__device__ __forceinline__ float2 unpack2h(unsigned int u) {
    return __half22float2(*reinterpret_cast<__half2*>(&u));
}
__device__ __forceinline__ unsigned long long pk(float lo, float hi) {
    unsigned long long r;
    asm("mov.b64 %0, {%1, %2};" : "=l"(r) : "f"(lo), "f"(hi));
    return r;
}
__device__ __forceinline__ float2 upk(unsigned long long v) {
    float2 r;
    asm("mov.b64 {%0, %1}, %2;" : "=f"(r.x), "=f"(r.y) : "l"(v));
    return r;
}
__device__ __forceinline__ unsigned long long mul2(unsigned long long a,
                                                   unsigned long long b) {
    unsigned long long r;
    asm("mul.rn.f32x2 %0, %1, %2;" : "=l"(r) : "l"(a), "l"(b));
    return r;
}
__device__ __forceinline__ unsigned long long fma2(unsigned long long a,
                                                   unsigned long long b,
                                                   unsigned long long c) {
    unsigned long long r;
    asm("fma.rn.f32x2 %0, %1, %2, %3;" : "=l"(r) : "l"(a), "l"(b), "l"(c));
    return r;
}
// 32B y load, L2 evict_last (persist vs concurrent fill streaming).
__device__ __forceinline__ void ldg_y_el(const __half* p, unsigned long long* q) {
    asm volatile("ld.global.nc.L2::evict_last.v4.b64 {%0,%1,%2,%3}, [%4];"
                 : "=l"(q[0]), "=l"(q[1]), "=l"(q[2]), "=l"(q[3]) : "l"(p));
}
// 32B y load, normal priority (FINAL sweep: last read of the group's y).
__device__ __forceinline__ void ldg_y_nm(const __half* p, unsigned long long* q) {
    asm volatile("ld.global.nc.v4.b64 {%0,%1,%2,%3}, [%4];"
                 : "=l"(q[0]), "=l"(q[1]), "=l"(q[2]), "=l"(q[3]) : "l"(p));
}

// ---------------- fill kernel: y = m*x (fp16) + sigma1 partials -----------
__global__ void __launch_bounds__(256, 4) fill_kernel(
    const float* x, const float* __restrict__ m, int b0) {
    const int b = b0 + blockIdx.y;
    const int c = blockIdx.x;
    const int t = threadIdx.x, w = t >> 5, l = t & 31;
    const int n0 = c * ROWS;

    __shared__ float m_sh[ROWS];
    __shared__ float sm_acc[WARPS * Dd];

    if (t < ROWS) m_sh[t] = m[b * Nn + n0 + t];
    __syncthreads();

    const size_t rowbase = (size_t)b * Nn + n0;
    const float* xb = x + rowbase * Dd;
    const int d0 = l << 2;

    float4 pa[PFF], pb[PFF];
#pragma unroll
    for (int j = 0; j < PFF; j++) {
        const float* xr = xb + (size_t)(w * RPW + j) * Dd;
        pa[j] = *reinterpret_cast<const float4*>(xr + d0);
        pb[j] = *reinterpret_cast<const float4*>(xr + 128 + d0);
    }

    float acc[8] = {0, 0, 0, 0, 0, 0, 0, 0};
#pragma unroll
    for (int i = 0; i < RPW; i++) {
        const int n = w * RPW + i;
        const float4 a0 = pa[i % PFF];
        const float4 a1 = pb[i % PFF];
        if (i + PFF < RPW) {
            const float* xn = xb + (size_t)(n + PFF) * Dd;
            pa[i % PFF] = *reinterpret_cast<const float4*>(xn + d0);
            pb[i % PFF] = *reinterpret_cast<const float4*>(xn + 128 + d0);
        }
        const float mn = m_sh[n];
        const float y0 = mn * a0.x, y1 = mn * a0.y, y2 = mn * a0.z, y3 = mn * a0.w;
        const float y4 = mn * a1.x, y5 = mn * a1.y, y6 = mn * a1.z, y7 = mn * a1.w;
        acc[0] += y0; acc[1] += y1; acc[2] += y2; acc[3] += y3;
        acc[4] += y4; acc[5] += y5; acc[6] += y6; acc[7] += y7;
        uint2 ua = make_uint2(pack2h(y0, y1), pack2h(y2, y3));
        uint2 ub = make_uint2(pack2h(y4, y5), pack2h(y6, y7));
        __half* yr = g_y + (rowbase + n) * Dd;
        *reinterpret_cast<uint2*>(yr + d0) = ua;
        *reinterpret_cast<uint2*>(yr + 128 + d0) = ub;
    }

    *reinterpret_cast<float4*>(&sm_acc[w * Dd + d0]) =
        make_float4(acc[0], acc[1], acc[2], acc[3]);
    *reinterpret_cast<float4*>(&sm_acc[w * Dd + 128 + d0]) =
        make_float4(acc[4], acc[5], acc[6], acc[7]);
    __syncthreads();

    float sig = 0.0f;
#pragma unroll
    for (int k = 0; k < WARPS; k++) sig += sm_acc[k * Dd + t];
    g_part[((size_t)b * NCHUNK + c) * Dd + t] = sig;
    if (t == 0) g_Z[b * NCHUNK + c] = (float)ROWS;  // uniform weights mass
}

// ------------- reuse kernel: head-combine -> s; b += dot; sigma ----------
// Half-warp row pairs: lanes 0-15 handle row (pair,half=0), 16-31 half=1.
// Lane owns 16 consecutive cols (32 bytes) -> one v4.b64 per warp per pair.
template <bool FINAL, bool ZEROB>
__global__ void __launch_bounds__(256, 4) reuse_kernel(
    const float* __restrict__ m, int b0, float* __restrict__ out_s) {
    const int b = b0 + blockIdx.y;
    const int c = blockIdx.x;
    const int t = threadIdx.x, w = t >> 5, l = t & 31;
    const int hl = l & 15, half = l >> 4;
    const int n0 = c * ROWS;

    __shared__ float s_sh[Dd];
    __shared__ float m_sh[ROWS];
    __shared__ float b_sh[ROWS];
    __shared__ float sm_acc[WARPS * Dd];
    __shared__ float sm_Z[WARPS];
    __shared__ float red[256];
    __shared__ float hz[NCHUNK];

    {
        int gi = b * Nn + n0;
        if (t < ROWS) {
            m_sh[t] = m[gi + t];
            b_sh[t] = ZEROB ? 0.0f : g_b[gi + t];
        }
    }
    // head-combine: rebuild s from previous sweep's partials
    if (t < NCHUNK) hz[t] = g_Z[b * NCHUNK + t];
    __syncthreads();
    {
        float v = 0.0f, Zg = 0.0f;
#pragma unroll
        for (int k = 0; k < NCHUNK; k++) {
            v += g_part[((size_t)b * NCHUNK + k) * Dd + t];
            Zg += hz[k];
        }
        const float sigma = v / Zg;
        red[t] = sigma * sigma;
        __syncthreads();
#pragma unroll
        for (int s = 128; s > 0; s >>= 1) {
            if (t < s) red[t] += red[t + s];
            __syncthreads();
        }
        const float n2 = red[0];
        const float norm = sqrtf(n2);
        const float sv = (n2 / (1.0f + n2) / (norm + 1e-8f)) * sigma;
        s_sh[t] = sv;
        if (FINAL && c == 0 && out_s) out_s[b * Dd + t] = sv;
    }
    __syncthreads();

    const size_t rowbase = (size_t)b * Nn + n0;
    const __half* yb = g_y + rowbase * Dd;
    const int col0 = hl << 4;  // lane owns cols col0..col0+15

    // s for this lane's 16 cols, packed f32x2
    unsigned long long sp[8];
#pragma unroll
    for (int j = 0; j < 8; j++)
        sp[j] = pk(s_sh[col0 + 2 * j], s_sh[col0 + 2 * j + 1]);

    const int r0 = w * RPW;  // warp's 16 rows = 8 pairs

    unsigned long long q[PFR][4];
#pragma unroll
    for (int j = 0; j < PFR; j++) {
        const __half* p = yb + (size_t)(r0 + 2 * j + half) * Dd + col0;
        if (FINAL) ldg_y_nm(p, q[j]); else ldg_y_el(p, q[j]);
    }

    unsigned long long ac[8] = {0, 0, 0, 0, 0, 0, 0, 0};
    float Z = 0.0f;

#pragma unroll
    for (int p = 0; p < PAIRS; p++) {
        unsigned long long cq0 = q[p % PFR][0], cq1 = q[p % PFR][1],
                           cq2 = q[p % PFR][2], cq3 = q[p % PFR][3];
        if (p + PFR < PAIRS) {
            const __half* np = yb + (size_t)(r0 + 2 * (p + PFR) + half) * Dd + col0;
            if (FINAL) ldg_y_nm(np, q[p % PFR]); else ldg_y_el(np, q[p % PFR]);
        }

        // unpack 16 halfs -> 8 packed f32x2
        unsigned long long yp[8];
        {
            const unsigned long long cc[4] = {cq0, cq1, cq2, cq3};
#pragma unroll
            for (int j = 0; j < 4; j++) {
                unsigned int lo, hi;
                asm("mov.b64 {%0,%1}, %2;" : "=r"(lo), "=r"(hi) : "l"(cc[j]));
                const float2 a = unpack2h(lo), d = unpack2h(hi);
                yp[2 * j]     = pk(a.x, a.y);
                yp[2 * j + 1] = pk(d.x, d.y);
            }
        }

        // dot over lane's 16 cols, then width-16 butterfly (4 shfl)
        unsigned long long d2 = mul2(yp[0], sp[0]);
#pragma unroll
        for (int j = 1; j < 8; j++) d2 = fma2(yp[j], sp[j], d2);
        const float2 dd = upk(d2);
        float dot = dd.x + dd.y;
#pragma unroll
        for (int o = 8; o > 0; o >>= 1)
            dot += __shfl_xor_sync(0xffffffffu, dot, o);

        const int n = r0 + 2 * p + half;
        const float bnew = b_sh[n] + dot;        // y already includes m
        if (hl == 0) g_b[b * Nn + n0 + n] = bnew;

        if (!FINAL) {
            const float e = __expf(m_sh[n] * bnew);  // raw weight (|logit|<=~24)
            Z += e;
            const unsigned long long e2 = pk(e, e);
#pragma unroll
            for (int j = 0; j < 8; j++) ac[j] = fma2(e2, yp[j], ac[j]);
        }
    }

    if (!FINAL) {
        // combine the two halves' partials (same cols), lanes 0-15 store
#pragma unroll
        for (int j = 0; j < 8; j++) {
            float2 a = upk(ac[j]);
            a.x += __shfl_xor_sync(0xffffffffu, a.x, 16);
            a.y += __shfl_xor_sync(0xffffffffu, a.y, 16);
            if (half == 0) {
                sm_acc[w * Dd + col0 + 2 * j]     = a.x;
                sm_acc[w * Dd + col0 + 2 * j + 1] = a.y;
            }
        }
        const float Zp = __shfl_xor_sync(0xffffffffu, Z, 16);
        if (l == 0) sm_Z[w] = Z + Zp;
        __syncthreads();

        float sig = 0.0f;
#pragma unroll
        for (int k = 0; k < WARPS; k++) sig += sm_acc[k * Dd + t];
        g_part[((size_t)b * NCHUNK + c) * Dd + t] = sig;
        if (t == 0) {
            float Zb = 0.0f;
#pragma unroll
            for (int k = 0; k < WARPS; k++) Zb += sm_Z[k];
            g_Z[b * NCHUNK + c] = Zb;
        }
    }
}

// Final w = softmax(b) over N (no m factor). Exact 2-pass in-register.
__global__ void __launch_bounds__(256) final_softmax_kernel(float* __restrict__ out_w) {
    const int b = blockIdx.x, t = threadIdx.x;
    const float* bb = g_b + (size_t)b * Nn;

    float vals[16];
    float lmax = -3.4e38f;
#pragma unroll
    for (int i = 0; i < 16; i++) {
        vals[i] = bb[t + i * 256];
        lmax = fmaxf(lmax, vals[i]);
    }
    __shared__ float red[256];
    red[t] = lmax;
    __syncthreads();
#pragma unroll
    for (int s = 128; s > 0; s >>= 1) {
        if (t < s) red[t] = fmaxf(red[t], red[t + s]);
        __syncthreads();
    }
    const float gmax = red[0];
    __syncthreads();

    float lsum = 0.0f;
#pragma unroll
    for (int i = 0; i < 16; i++) {
        vals[i] = __expf(vals[i] - gmax);
        lsum += vals[i];
    }
    red[t] = lsum;
    __syncthreads();
#pragma unroll
    for (int s = 128; s > 0; s >>= 1) {
        if (t < s) red[t] += red[t + s];
        __syncthreads();
    }
    const float inv = 1.0f / red[0];
#pragma unroll
    for (int i = 0; i < 16; i++)
        out_w[(size_t)b * Nn + t + i * 256] = vals[i] * inv;
}

extern "C" void kernel_launch(void* const* d_in, const int* in_sizes, int n_in,
                              void* d_out, int out_size) {
    (void)in_sizes; (void)n_in; (void)out_size;
    const float* x = (const float*)d_in[0];
    const float* m = (const float*)d_in[1];
    float* out = (float*)d_out;
    float* out_w = out;             // [B, N]
    float* out_s = out + Bb * Nn;   // [B, D]

    const dim3 grid(NCHUNK, GRP);

    // Fork side stream into the capture.
    cudaEventRecord(g_kit.ev_root, 0);
    cudaStreamWaitEvent(g_kit.s1, g_kit.ev_root, 0);

    for (int g = 0; g < NGRP; ++g) {
        fill_kernel<<<grid, 256, 0, g_kit.s1>>>(x, m, g * GRP);
        cudaEventRecord(g_kit.ev_fill[g], g_kit.s1);
    }

    for (int g = 0; g < NGRP; ++g) {
        const int b0 = g * GRP;
        cudaStreamWaitEvent(0, g_kit.ev_fill[g], 0);
        reuse_kernel<false, true><<<grid, 256>>>(m, b0, nullptr);   // b1+sigma2
        reuse_kernel<false, false><<<grid, 256>>>(m, b0, nullptr);  // b2+sigma3
        reuse_kernel<true, false><<<grid, 256>>>(m, b0, out_s);     // s3+b3
    }
    final_softmax_kernel<<<Bb, 256>>>(out_w);  // w = softmax(b3)
}